// round 14
// baseline (speedup 1.0000x reference)
#include <cuda_runtime.h>
#include <cuda_fp16.h>
#include <cstdint>

#define BATCH 2
#define SEQ   2048
#define DIM   2048
#define NH    16
#define NKV   4
#define HD    128
#define KVDIM (NKV*HD)      // 512
#define MS    (BATCH*SEQ)   // 4096

// ---- scratch (device globals; no allocation allowed) ----
__device__ half  g_xh [MS * DIM];
__device__ half  g_wqh[DIM * DIM];
__device__ half  g_wkh[DIM * KVDIM];
__device__ half  g_wvh[DIM * KVDIM];
__device__ half  g_woh[DIM * DIM];
__device__ half  g_qh [MS * DIM];
__device__ half  g_kh [MS * KVDIM];
__device__ half  g_vh [MS * KVDIM];
__device__ half  g_atth[MS * DIM];

// ===========================================================================
// primitives
// ===========================================================================
__device__ __forceinline__ uint32_t smem_u32(const void* p) {
    uint32_t a;
    asm("{ .reg .u64 t; cvta.to.shared.u64 t, %1; cvt.u32.u64 %0, t; }"
        : "=r"(a) : "l"(p));
    return a;
}
__device__ __forceinline__ void ldmx4(uint32_t* r, uint32_t addr) {
    asm volatile("ldmatrix.sync.aligned.m8n8.x4.shared.b16 {%0,%1,%2,%3}, [%4];"
                 : "=r"(r[0]), "=r"(r[1]), "=r"(r[2]), "=r"(r[3]) : "r"(addr));
}
__device__ __forceinline__ void ldmx4t(uint32_t* r, uint32_t addr) {
    asm volatile("ldmatrix.sync.aligned.m8n8.x4.trans.shared.b16 {%0,%1,%2,%3}, [%4];"
                 : "=r"(r[0]), "=r"(r[1]), "=r"(r[2]), "=r"(r[3]) : "r"(addr));
}
__device__ __forceinline__ void mma_f16(float* c, const uint32_t* a,
                                        const uint32_t* b) {
    asm volatile(
        "mma.sync.aligned.m16n8k16.row.col.f32.f16.f16.f32 "
        "{%0,%1,%2,%3}, {%4,%5,%6,%7}, {%8,%9}, {%0,%1,%2,%3};"
        : "+f"(c[0]), "+f"(c[1]), "+f"(c[2]), "+f"(c[3])
        : "r"(a[0]), "r"(a[1]), "r"(a[2]), "r"(a[3]), "r"(b[0]), "r"(b[1]));
}
__device__ __forceinline__ void cpasync16(uint32_t dst, const void* src) {
    asm volatile("cp.async.cg.shared.global [%0], [%1], 16;"
                 :: "r"(dst), "l"(src));
}
#define CP_COMMIT() asm volatile("cp.async.commit_group;" ::: "memory")
#define CP_WAIT(n)  asm volatile("cp.async.wait_group %0;" :: "n"(n) : "memory")

// ---------------------------------------------------------------------------
// f2h_multi: one launch converting all 5 fp32 operands to fp16.
// ---------------------------------------------------------------------------
__global__ void f2h_multi(const float* __restrict__ x,  half* __restrict__ xh,
                          const float* __restrict__ wq, half* __restrict__ wqh,
                          const float* __restrict__ wk, half* __restrict__ wkh,
                          const float* __restrict__ wv, half* __restrict__ wvh,
                          const float* __restrict__ wo, half* __restrict__ woh)
{
    const float* s; half* d; int n4;
    switch (blockIdx.y) {
        case 0: s = x;  d = xh;  n4 = MS * DIM / 4;    break;
        case 1: s = wq; d = wqh; n4 = DIM * DIM / 4;   break;
        case 2: s = wk; d = wkh; n4 = DIM * KVDIM / 4; break;
        case 3: s = wv; d = wvh; n4 = DIM * KVDIM / 4; break;
        default:s = wo; d = woh; n4 = DIM * DIM / 4;   break;
    }
    int i = blockIdx.x * blockDim.x + threadIdx.x;
    if (i >= n4) return;
    float4 v = ((const float4*)s)[i];
    ((half2*)d)[2 * i]     = __floats2half2_rn(v.x, v.y);
    ((half2*)d)[2 * i + 1] = __floats2half2_rn(v.z, v.w);
}

// ===========================================================================
// fp16 GEMM core: CTA 128x256, BK=32, 4-stage cp.async, one barrier/K-tile.
// 256 thr, 8 warps 2(M)x4(N), warp tile 64x64 (acc 128 regs, 1 CTA/SM).
// A smem stride 80B, B smem stride 528B (both ldmatrix conflict-free).
// Epilogue modes: 0 = fp32 store; 1 = RoPE+scale -> fp16 (q);
//                 2 = RoPE -> fp16 (k); 3 = plain fp16 (v).
// ===========================================================================
#define BN_T   256
#define AST_B  (128 * 80)           // 10240
#define BST_B  (32 * 528)           // 16896
#define STAGE_B (AST_B + BST_B)     // 27136
#define NSTAGE 4
#define GSMEM  (NSTAGE * STAGE_B)   // 108544

__device__ __forceinline__ void gemm_core_h(const half* __restrict__ Ah,
                                            const half* __restrict__ Bh,
                                            float* __restrict__ Cf,
                                            half* __restrict__ Ch,
                                            int N, int K, int bm, int bn,
                                            int mode,
                                            const float* __restrict__ fc,
                                            const float* __restrict__ fs)
{
    extern __shared__ char smem[];
    uint32_t sb = smem_u32(smem);
    int tid = threadIdx.x, lane = tid & 31, wid = tid >> 5;
    int wm = (wid >> 2) * 64, wn = (wid & 3) * 64;

    float acc[4][8][4];
#pragma unroll
    for (int mi = 0; mi < 4; mi++)
#pragma unroll
        for (int ni = 0; ni < 8; ni++)
#pragma unroll
            for (int c = 0; c < 4; c++) acc[mi][ni][c] = 0.f;

    auto issue = [&](int s) {
        int k0 = s << 5;
        uint32_t base = sb + (s % NSTAGE) * STAGE_B;
        // A: 128 rows x 64 B  (512 x 16B chunks, 2 per thread)
#pragma unroll
        for (int l = 0; l < 2; l++) {
            int idx = tid + l * 256;
            int row = idx >> 2, ch = idx & 3;
            cpasync16(base + row * 80 + ch * 16,
                      (const char*)Ah + ((size_t)(bm + row) * K + k0) * 2 + ch * 16);
        }
        // B: 32 rows x 512 B  (1024 x 16B chunks, 4 per thread)
#pragma unroll
        for (int l = 0; l < 4; l++) {
            int idx = tid + l * 256;
            int br = idx >> 5, bch = idx & 31;
            cpasync16(base + AST_B + br * 528 + bch * 16,
                      (const char*)Bh + ((size_t)(k0 + br) * N + bn) * 2 + bch * 16);
        }
    };

    int niter = K >> 5;
    issue(0); CP_COMMIT();
    issue(1); CP_COMMIT();
    issue(2); CP_COMMIT();

    for (int i = 0; i < niter; i++) {
        // ensure group i complete (pending afterwards: i+1, i+2)
        if (i + 2 < niter) CP_WAIT(2);
        else if (i + 1 < niter) CP_WAIT(1);
        else CP_WAIT(0);
        // one barrier: stage-i visible + stage i-1 (buffer (i+3)%4) fully
        // consumed by all warps before the next issue overwrites it
        __syncthreads();
        if (i + 3 < niter) { issue(i + 3); CP_COMMIT(); }

        uint32_t ab = sb + (i % NSTAGE) * STAGE_B;
        uint32_t bb = ab + AST_B;
#pragma unroll
        for (int ks = 0; ks < 2; ks++) {
            uint32_t af[4][4], bf[4][4];
#pragma unroll
            for (int mi = 0; mi < 4; mi++)
                ldmx4(af[mi], ab + (wm + mi * 16 + (lane & 15)) * 80
                               + ks * 32 + ((lane >> 4) << 4));
#pragma unroll
            for (int nh = 0; nh < 4; nh++)
                ldmx4t(bf[nh], bb + (ks * 16 + (lane & 7) + ((lane >> 3) & 1) * 8) * 528
                                + (wn + nh * 16 + ((lane >> 4) << 3)) * 2);
#pragma unroll
            for (int mi = 0; mi < 4; mi++)
#pragma unroll
                for (int ni = 0; ni < 8; ni++)
                    mma_f16(acc[mi][ni], af[mi], &bf[ni >> 1][(ni & 1) * 2]);
        }
    }

    int r = bm + wm + (lane >> 2);
    int c = bn + wn + (lane & 3) * 2;

    if (mode == 0) {
#pragma unroll
        for (int mi = 0; mi < 4; mi++) {
#pragma unroll
            for (int ni = 0; ni < 8; ni++) {
                *(float2*)(Cf + (size_t)(r + mi * 16)     * N + c + ni * 8) =
                    make_float2(acc[mi][ni][0], acc[mi][ni][1]);
                *(float2*)(Cf + (size_t)(r + mi * 16 + 8) * N + c + ni * 8) =
                    make_float2(acc[mi][ni][2], acc[mi][ni][3]);
            }
        }
        return;
    }

    // fp16 epilogue (optionally fused RoPE; head=128 divides all offsets)
    const float sc = 0.08838834764831845f;  // 1/sqrt(128)
#pragma unroll
    for (int mi = 0; mi < 4; mi++) {
        int row0 = r + mi * 16, row1 = row0 + 8;
#pragma unroll
        for (int ni = 0; ni < 8; ni++) {
            int cg = c + ni * 8;
            float a0 = acc[mi][ni][0], a1 = acc[mi][ni][1];
            float a2 = acc[mi][ni][2], a3 = acc[mi][ni][3];
            if (mode < 3) {
                int p = (cg & 127) >> 1;
                int sq0 = row0 & (SEQ - 1), sq1 = row1 & (SEQ - 1);
                float c0 = fc[sq0 * 64 + p], s0 = fs[sq0 * 64 + p];
                float c1 = fc[sq1 * 64 + p], s1 = fs[sq1 * 64 + p];
                float r0 = a0 * c0 - a1 * s0, i0 = a0 * s0 + a1 * c0;
                float r1 = a2 * c1 - a3 * s1, i1 = a2 * s1 + a3 * c1;
                if (mode == 1) { r0 *= sc; i0 *= sc; r1 *= sc; i1 *= sc; }
                a0 = r0; a1 = i0; a2 = r1; a3 = i1;
            }
            *(half2*)(Ch + (size_t)row0 * N + cg) = __floats2half2_rn(a0, a1);
            *(half2*)(Ch + (size_t)row1 * N + cg) = __floats2half2_rn(a2, a3);
        }
    }
}

// Fused QKV + RoPE: grid.x = 8 (q) + 2 (k) + 2 (v) 256-col blocks.
__global__ __launch_bounds__(256, 1) void qkv_mma(const half* __restrict__ xh,
                                                  const float* __restrict__ fc,
                                                  const float* __restrict__ fs)
{
    int bx = blockIdx.x, bm = blockIdx.y << 7;
    const half* B; half* D; int N, bn, mode;
    if (bx < 8)       { B = g_wqh; D = g_qh; N = DIM;   bn = bx << 8;        mode = 1; }
    else if (bx < 10) { B = g_wkh; D = g_kh; N = KVDIM; bn = (bx - 8) << 8;  mode = 2; }
    else              { B = g_wvh; D = g_vh; N = KVDIM; bn = (bx - 10) << 8; mode = 3; }
    gemm_core_h(xh, B, nullptr, D, N, DIM, bm, bn, mode, fc, fs);
}

__global__ __launch_bounds__(256, 1) void out_mma(const half* __restrict__ Ah,
                                                  const half* __restrict__ Bh,
                                                  float* __restrict__ C,
                                                  int N, int K)
{
    gemm_core_h(Ah, Bh, C, nullptr, N, K, blockIdx.y << 7, blockIdx.x << 8,
                0, nullptr, nullptr);
}

// ===========================================================================
// FA2-style flash attention: CTA = 128 q-rows x one (b,h), 8 warps x 16 rows.
// S in registers; softmax via quad shuffles; K/V double-buffered cp.async;
// ONE barrier per KV tile; fp16 output.
// ===========================================================================
#define Q_OFF  0                    // 128*272 = 34816
#define K_OFF  34816                // 2 stages x 64*272
#define V_OFF  69632                // 2 stages x 64*272
#define ATT_SMEM 104448

__global__ __launch_bounds__(256, 1) void attn_fa2(const half* __restrict__ Qh,
                                                   const half* __restrict__ Kh,
                                                   const half* __restrict__ Vh,
                                                   half* __restrict__ Oh)
{
    extern __shared__ char smem[];
    uint32_t sbu = smem_u32(smem);

    int tid = threadIdx.x, lane = tid & 31, wid = tid >> 5;
    int wm = wid * 16;
    int mblk = gridDim.x - 1 - blockIdx.x;   // long CTAs first
    int bh = blockIdx.y;
    int b = bh >> 4, h = bh & 15;
    int g = h >> 2;
    int m0 = mblk * 128;

    const char* qsrc = (const char*)Qh + ((size_t)(b * SEQ + m0) * DIM + h * HD) * 2;

    // ---- issue Q (group 0) ----
#pragma unroll
    for (int l = 0; l < 8; l++) {
        int idx = tid + l * 256;
        int row = idx >> 4, ch = idx & 15;
        cpasync16(sbu + Q_OFF + row * 272 + ch * 16,
                  qsrc + (size_t)row * DIM * 2 + ch * 16);
    }
    CP_COMMIT();

    auto issue_kv = [&](int it) {
        int n0 = it * 64, st = it & 1;
        const char* ks = (const char*)Kh + ((size_t)(b * SEQ + n0) * KVDIM + g * HD) * 2;
        const char* vs = (const char*)Vh + ((size_t)(b * SEQ + n0) * KVDIM + g * HD) * 2;
        uint32_t kd = sbu + K_OFF + st * 17408;
        uint32_t vd = sbu + V_OFF + st * 17408;
#pragma unroll
        for (int l = 0; l < 4; l++) {
            int idx = tid + l * 256;
            int row = idx >> 4, ch = idx & 15;
            cpasync16(kd + row * 272 + ch * 16, ks + (size_t)row * KVDIM * 2 + ch * 16);
            cpasync16(vd + row * 272 + ch * 16, vs + (size_t)row * KVDIM * 2 + ch * 16);
        }
    };
    issue_kv(0); CP_COMMIT();       // group 1

    CP_WAIT(1);                     // Q done (KV0 may be pending)
    __syncthreads();

    // ---- Q fragments to registers (once) ----
    uint32_t qf[8][4];
#pragma unroll
    for (int ks = 0; ks < 8; ks++)
        ldmx4(qf[ks], sbu + Q_OFF + (wm + (lane & 15)) * 272
                       + ks * 32 + ((lane >> 4) << 4));

    float oacc[16][4];
#pragma unroll
    for (int t = 0; t < 16; t++)
#pragma unroll
        for (int c = 0; c < 4; c++) oacc[t][c] = 0.f;
    float m_lo = -1e30f, m_hi = -1e30f, l_lo = 0.f, l_hi = 0.f;

    int niter = 2 * mblk + 2;
    for (int i = 0; i < niter; i++) {
        CP_WAIT(0);                             // KV stage i arrived
        __syncthreads();
        if (i + 1 < niter) { issue_kv(i + 1); CP_COMMIT(); }

        int n0 = i * 64;
        uint32_t kb = sbu + K_OFF + (i & 1) * 17408;
        uint32_t vb = sbu + V_OFF + (i & 1) * 17408;

        if (n0 <= m0 + wm + 15) {                // warp-uniform skip
            // ---- S = Q K^T ----
            float sacc[8][4];
#pragma unroll
            for (int t = 0; t < 8; t++)
#pragma unroll
                for (int c = 0; c < 4; c++) sacc[t][c] = 0.f;
#pragma unroll
            for (int ks = 0; ks < 8; ks++) {
                uint32_t bf[4][4];
#pragma unroll
                for (int nh = 0; nh < 4; nh++)
                    ldmx4(bf[nh], kb + (nh * 16 + ((lane >> 4) << 3) + (lane & 7)) * 272
                                   + ks * 32 + (((lane >> 3) & 1) << 4));
#pragma unroll
                for (int t = 0; t < 8; t++)
                    mma_f16(sacc[t], qf[ks], &bf[t >> 1][(t & 1) * 2]);
            }
            // ---- causal mask (only near diagonal) ----
            if (n0 + 63 > m0 + wm) {
                int r0 = m0 + wm + (lane >> 2);
#pragma unroll
                for (int t = 0; t < 8; t++) {
                    int c0 = n0 + 8 * t + 2 * (lane & 3);
                    if (c0     > r0)     sacc[t][0] = -1e30f;
                    if (c0 + 1 > r0)     sacc[t][1] = -1e30f;
                    if (c0     > r0 + 8) sacc[t][2] = -1e30f;
                    if (c0 + 1 > r0 + 8) sacc[t][3] = -1e30f;
                }
            }
            // ---- register online softmax (quad shuffles) ----
            float rm_lo = -1e30f, rm_hi = -1e30f;
#pragma unroll
            for (int t = 0; t < 8; t++) {
                rm_lo = fmaxf(rm_lo, fmaxf(sacc[t][0], sacc[t][1]));
                rm_hi = fmaxf(rm_hi, fmaxf(sacc[t][2], sacc[t][3]));
            }
            rm_lo = fmaxf(rm_lo, __shfl_xor_sync(0xffffffffu, rm_lo, 1));
            rm_lo = fmaxf(rm_lo, __shfl_xor_sync(0xffffffffu, rm_lo, 2));
            rm_hi = fmaxf(rm_hi, __shfl_xor_sync(0xffffffffu, rm_hi, 1));
            rm_hi = fmaxf(rm_hi, __shfl_xor_sync(0xffffffffu, rm_hi, 2));
            float nm_lo = fmaxf(m_lo, rm_lo), nm_hi = fmaxf(m_hi, rm_hi);
            float cf_lo = __expf(m_lo - nm_lo), cf_hi = __expf(m_hi - nm_hi);
            m_lo = nm_lo; m_hi = nm_hi;

            float sum_lo = 0.f, sum_hi = 0.f;
            uint32_t pf[4][4];
#pragma unroll
            for (int t = 0; t < 8; t++) {
                float p0 = __expf(sacc[t][0] - nm_lo);
                float p1 = __expf(sacc[t][1] - nm_lo);
                float p2 = __expf(sacc[t][2] - nm_hi);
                float p3 = __expf(sacc[t][3] - nm_hi);
                sum_lo += p0 + p1; sum_hi += p2 + p3;
                half2 h01 = __floats2half2_rn(p0, p1);
                half2 h23 = __floats2half2_rn(p2, p3);
                pf[t >> 1][(t & 1) * 2]     = *(uint32_t*)&h01;
                pf[t >> 1][(t & 1) * 2 + 1] = *(uint32_t*)&h23;
            }
            sum_lo += __shfl_xor_sync(0xffffffffu, sum_lo, 1);
            sum_lo += __shfl_xor_sync(0xffffffffu, sum_lo, 2);
            sum_hi += __shfl_xor_sync(0xffffffffu, sum_hi, 1);
            sum_hi += __shfl_xor_sync(0xffffffffu, sum_hi, 2);
            l_lo = l_lo * cf_lo + sum_lo;
            l_hi = l_hi * cf_hi + sum_hi;
#pragma unroll
            for (int t = 0; t < 16; t++) {
                oacc[t][0] *= cf_lo; oacc[t][1] *= cf_lo;
                oacc[t][2] *= cf_hi; oacc[t][3] *= cf_hi;
            }
            // ---- O += P V ----
#pragma unroll
            for (int ks = 0; ks < 4; ks++) {
                uint32_t bv[8][4];
#pragma unroll
                for (int nh = 0; nh < 8; nh++)
                    ldmx4t(bv[nh], vb + (ks * 16 + (lane & 7) + ((lane >> 3) & 1) * 8) * 272
                                    + (nh * 16 + ((lane >> 4) << 3)) * 2);
#pragma unroll
                for (int t = 0; t < 16; t++)
                    mma_f16(oacc[t], pf[ks], &bv[t >> 1][(t & 1) * 2]);
            }
        }
    }

    // ---- finalize: write fp16 output ----
    float inv_lo = 1.f / l_lo, inv_hi = 1.f / l_hi;
    int r0 = m0 + wm + (lane >> 2);
    half* ob0 = Oh + (size_t)(b * SEQ + r0) * DIM + h * HD;
    half* ob1 = ob0 + (size_t)8 * DIM;
#pragma unroll
    for (int t = 0; t < 16; t++) {
        int cb = 8 * t + 2 * (lane & 3);
        half2 w0 = __floats2half2_rn(oacc[t][0] * inv_lo, oacc[t][1] * inv_lo);
        half2 w1 = __floats2half2_rn(oacc[t][2] * inv_hi, oacc[t][3] * inv_hi);
        *(half2*)(ob0 + cb) = w0;
        *(half2*)(ob1 + cb) = w1;
    }
}

// ---------------------------------------------------------------------------
extern "C" void kernel_launch(void* const* d_in, const int* in_sizes, int n_in,
                              void* d_out, int out_size)
{
    const float* x  = (const float*)d_in[0];
    const float* fc = (const float*)d_in[1];
    const float* fs = (const float*)d_in[2];
    const float* Wq = (const float*)d_in[3];
    const float* Wk = (const float*)d_in[4];
    const float* Wv = (const float*)d_in[5];
    const float* Wo = (const float*)d_in[6];
    float* out = (float*)d_out;

    half *xh, *wqh, *wkh, *wvh, *woh, *qh, *kh, *vh, *atth;
    cudaGetSymbolAddress((void**)&xh,   g_xh);
    cudaGetSymbolAddress((void**)&wqh,  g_wqh);
    cudaGetSymbolAddress((void**)&wkh,  g_wkh);
    cudaGetSymbolAddress((void**)&wvh,  g_wvh);
    cudaGetSymbolAddress((void**)&woh,  g_woh);
    cudaGetSymbolAddress((void**)&qh,   g_qh);
    cudaGetSymbolAddress((void**)&kh,   g_kh);
    cudaGetSymbolAddress((void**)&vh,   g_vh);
    cudaGetSymbolAddress((void**)&atth, g_atth);

    cudaFuncSetAttribute(qkv_mma,  cudaFuncAttributeMaxDynamicSharedMemorySize, GSMEM);
    cudaFuncSetAttribute(out_mma,  cudaFuncAttributeMaxDynamicSharedMemorySize, GSMEM);
    cudaFuncSetAttribute(attn_fa2, cudaFuncAttributeMaxDynamicSharedMemorySize, ATT_SMEM);

    // all fp32 -> fp16 converts, one launch (grid.y = segment)
    f2h_multi<<<dim3(MS * DIM / 4 / 256, 5), 256>>>(x, xh, Wq, wqh, Wk, wkh,
                                                    Wv, wvh, Wo, woh);

    // fused QKV projections + RoPE (fp16 out; q pre-scaled by 1/sqrt(d))
    qkv_mma<<<dim3(12, MS / 128), 256, GSMEM>>>(xh, fc, fs);

    // flash attention (fp16, register softmax) -> fp16 att
    attn_fa2<<<dim3(SEQ / 128, BATCH * NH), 256, ATT_SMEM>>>(qh, kh, vh, atth);

    // output projection (fp32 out)
    out_mma<<<dim3(DIM / 256, MS / 128), 256, GSMEM>>>(atth, woh, out, DIM, DIM);
}